// round 8
// baseline (speedup 1.0000x reference)
#include <cuda_runtime.h>
#include <math.h>

#define B_    32
#define T_    10
#define N_    1000
#define C_    96
#define E_    8000
#define G_    (B_*T_)      // 320
#define ETOT  (E_+N_)      // 9000
#define C4_   (C_/4)       // 24
#define CP_   (C_/2)       // 48 channel pairs

// k_edge tiling
#define CHUNK 8            // channels per phase
#define NPH   (C_/CHUNK)   // 12 phases
#define PPH   (CHUNK/2)    // 4 pairs per phase
#define TPE   512          // threads per edge-block
#define HALF  (ETOT/2)     // 4500 slots per block
#define EPT   9            // ceil(4500/512)

// k_out tiling
#define ONODES 20          // nodes per out-block
#define OTPB   (ONODES*C4_) // 480 threads

// ---- device scratch ----
__device__ ulonglong2 g_Pa[CP_];       // {Wl2, Wr2} packed f32x2 per channel pair
__device__ ulonglong2 g_Pb[CP_];       // {K2,  A2 } K=bl+br, A=0.4*att
__device__ float      g_scal[3];       // 0.6*<att,Wl>, 0.6*<att,Wr>, 0.6*<att,bl+br>
__device__ float4     g_add4[T_*C4_];  // bl+bias+pos per (t, c/4)
__device__ int        g_off[N_+1];
__device__ int4       g_sd4[ETOT/2];   // (src,dst) pairs, 2 edges per int4
__device__ float      g_e[G_*ETOT];    // logits
__device__ float      g_S[G_*N_];      // softmax-weighted source mean

// ---------------------------------------------------------------------------
// Fused prep (unchanged from R7): params + dots + pos table + CSR
// ---------------------------------------------------------------------------
__device__ __forceinline__ int edge_dst(const int* EI, int e) {
    return (e < E_) ? EI[E_ + e] : (e - E_);
}
__device__ __forceinline__ int edge_src(const int* EI, int e) {
    return (e < E_) ? EI[e] : (e - E_);
}

__global__ void k_prep(const int* __restrict__ EI,
                       const float* __restrict__ Wl, const float* __restrict__ bl,
                       const float* __restrict__ Wr, const float* __restrict__ br,
                       const float* __restrict__ att, const float* __restrict__ bias) {
    __shared__ int   sdeg[1024];
    __shared__ int   soff[N_+1];
    __shared__ int   scnt[N_];
    __shared__ int   stmp[ETOT];
    __shared__ float sred[32];

    int tid  = threadIdx.x;
    int lane = tid & 31;
    int wid  = tid >> 5;

    float d0 = 0.f, d1 = 0.f, d2 = 0.f;
    if (tid < C_) {
        float a = att[tid];
        d0 = a * Wl[tid]; d1 = a * Wr[tid]; d2 = a * (bl[tid] + br[tid]);

        int   pair = tid >> 1;
        float freq = __expf(-(float)(2 * pair) * (logf(10000.f) / (float)C_));
        float badd = bl[tid] + bias[tid];
        float* addf = (float*)g_add4;
        for (int t = 0; t < T_; t++) {
            float arg = (float)t * freq;
            addf[t * C_ + tid] = badd + ((tid & 1) ? cosf(arg) : sinf(arg));
        }
    }
    if (tid < CP_) {
        int c0 = 2 * tid, c1 = 2 * tid + 1;
        float4 pa = make_float4(Wl[c0], Wl[c1], Wr[c0], Wr[c1]);
        float4 pb = make_float4(bl[c0] + br[c0], bl[c1] + br[c1],
                                0.4f * att[c0], 0.4f * att[c1]);
        ((float4*)g_Pa)[tid] = pa;
        ((float4*)g_Pb)[tid] = pb;
    }
    float vals[3] = {d0, d1, d2};
    for (int r = 0; r < 3; r++) {
        float v = vals[r];
        #pragma unroll
        for (int o = 16; o; o >>= 1) v += __shfl_down_sync(0xffffffffu, v, o);
        if (lane == 0) sred[wid] = v;
        __syncthreads();
        if (wid == 0) {
            float w = sred[lane];
            #pragma unroll
            for (int o = 16; o; o >>= 1) w += __shfl_down_sync(0xffffffffu, w, o);
            if (lane == 0) g_scal[r] = 0.6f * w;
        }
        __syncthreads();
    }

    sdeg[tid] = 0;
    if (tid < N_) scnt[tid] = 0;
    __syncthreads();
    for (int e = tid; e < ETOT; e += 1024)
        atomicAdd(&sdeg[edge_dst(EI, e)], 1);
    __syncthreads();

    for (int o = 1; o < 1024; o <<= 1) {
        int t = (tid >= o) ? sdeg[tid - o] : 0;
        __syncthreads();
        sdeg[tid] += t;
        __syncthreads();
    }
    if (tid == 0) soff[0] = 0;
    if (tid < N_) soff[tid + 1] = sdeg[tid];
    __syncthreads();
    if (tid <= N_) g_off[tid] = soff[tid];

    for (int e = tid; e < ETOT; e += 1024) {
        int d = edge_dst(EI, e);
        stmp[soff[d] + atomicAdd(&scnt[d], 1)] = e;
    }
    __syncthreads();

    if (tid < N_) {
        int lo = soff[tid], hi = soff[tid + 1];
        for (int a = lo + 1; a < hi; a++) {
            int key = stmp[a];
            int b = a - 1;
            while (b >= lo && stmp[b] > key) { stmp[b + 1] = stmp[b]; b--; }
            stmp[b + 1] = key;
        }
        int2* sd = (int2*)g_sd4;
        for (int a = lo; a < hi; a++)
            sd[a] = make_int2(edge_src(EI, stmp[a]), tid);
    }
}

// ---------------------------------------------------------------------------
// Packed f32x2 helpers
// ---------------------------------------------------------------------------
typedef unsigned long long ull;
__device__ __forceinline__ ull fma2(ull a, ull b, ull c) {
    ull d;
    asm("fma.rn.f32x2 %0, %1, %2, %3;" : "=l"(d) : "l"(a), "l"(b), "l"(c));
    return d;
}
__device__ __forceinline__ ull pack2(float v) {
    ull u;
    asm("mov.b64 %0, {%1, %1};" : "=l"(u) : "f"(v));
    return u;
}
__device__ __forceinline__ float sum2(ull u) {
    float lo, hi;
    asm("mov.b64 {%0, %1}, %2;" : "=f"(lo), "=f"(hi) : "l"(u));
    return lo + hi;
}
__device__ __forceinline__ float lo2(ull u) {
    float lo, hi;
    asm("mov.b64 {%0, %1}, %2;" : "=f"(lo), "=f"(hi) : "l"(u));
    return lo;
}
#define ABS2 0x7FFFFFFF7FFFFFFFULL

// ---------------------------------------------------------------------------
// Edge logits, 2-FMA/channel: per node precompute w_i = xi*Wr + K in smem
// (8 channels per phase, 12 phases), per edge: z = fma(xj, Wl, w_i); acc += A|z|
// block = (graph, half of CSR slots); e = lin + sum_c A|z|
// ---------------------------------------------------------------------------
__global__ __launch_bounds__(TPE) void k_edge(const float* __restrict__ x) {
    __shared__ ulonglong2 w_s[N_][2];      // 32 KB: per node, 4 packed pairs
    int g    = blockIdx.x >> 1;
    int half = blockIdx.x & 1;
    int base = half * HALF;
    int tid  = threadIdx.x;
    const float* xg = x + g * N_;

    float S0 = g_scal[0], S1 = g_scal[1], S2 = g_scal[2];

    int dst[EPT];
    ull xj2[EPT];
    ull acc[EPT];
    #pragma unroll
    for (int k = 0; k < EPT; k++) {
        int slot = base + tid + k * TPE;
        int2 sd = make_int2(0, 0);
        if (slot < base + HALF) sd = ((const int2*)g_sd4)[slot];
        dst[k] = sd.y;
        float xjv = (slot < base + HALF) ? __ldg(&xg[sd.x]) : 0.f;
        xj2[k] = pack2(xjv);
        acc[k] = 0ULL;
    }

    #pragma unroll 1
    for (int ph = 0; ph < NPH; ph++) {
        ull Wl2[PPH], A2[PPH], Wr2[PPH], K2[PPH];
        #pragma unroll
        for (int p = 0; p < PPH; p++) {
            ulonglong2 pa = g_Pa[ph * PPH + p];
            ulonglong2 pb = g_Pb[ph * PPH + p];
            Wl2[p] = pa.x; Wr2[p] = pa.y; K2[p] = pb.x; A2[p] = pb.y;
        }
        __syncthreads();   // previous phase readers done
        for (int n = tid; n < N_; n += TPE) {
            ull xn2 = pack2(xg[n]);
            ulonglong2 wa, wb;
            wa.x = fma2(xn2, Wr2[0], K2[0]);
            wa.y = fma2(xn2, Wr2[1], K2[1]);
            wb.x = fma2(xn2, Wr2[2], K2[2]);
            wb.y = fma2(xn2, Wr2[3], K2[3]);
            w_s[n][0] = wa;
            w_s[n][1] = wb;
        }
        __syncthreads();
        #pragma unroll
        for (int k = 0; k < EPT; k++) {
            ulonglong2 wa = w_s[dst[k]][0];
            ulonglong2 wb = w_s[dst[k]][1];
            ull z0 = fma2(xj2[k], Wl2[0], wa.x) & ABS2;
            ull z1 = fma2(xj2[k], Wl2[1], wa.y) & ABS2;
            ull z2 = fma2(xj2[k], Wl2[2], wb.x) & ABS2;
            ull z3 = fma2(xj2[k], Wl2[3], wb.y) & ABS2;
            acc[k] = fma2(A2[0], z0, acc[k]);
            acc[k] = fma2(A2[1], z1, acc[k]);
            acc[k] = fma2(A2[2], z2, acc[k]);
            acc[k] = fma2(A2[3], z3, acc[k]);
        }
    }

    #pragma unroll
    for (int k = 0; k < EPT; k++) {
        int slot = base + tid + k * TPE;
        if (slot < base + HALF) {
            float xi  = __ldg(&xg[dst[k]]);
            float xjf = lo2(xj2[k]);
            float lin = fmaf(S0, xjf, fmaf(S1, xi, S2));
            g_e[g * ETOT + slot] = lin + sum2(acc[k]);
        }
    }
}

// ---------------------------------------------------------------------------
// Per-node softmax (no max pass: logits bounded far below exp overflow)
// ---------------------------------------------------------------------------
__global__ void k_softmax(const float* __restrict__ x) {
    int tid = blockIdx.x * blockDim.x + threadIdx.x;
    if (tid >= G_ * N_) return;
    int g = tid / N_;
    int i = tid - g * N_;
    int lo = g_off[i], hi = g_off[i + 1];
    const float* eb = g_e + g * ETOT;
    const float* xg = x + g * N_;
    const int2*  sd = (const int2*)g_sd4;

    float num = 0.f, den = 0.f;
    for (int s = lo; s < hi; s++) {
        float w  = __expf(eb[s]);
        float xj = __ldg(&xg[sd[s].x]);
        num = fmaf(w, xj, num);
        den += w;
    }
    g_S[tid] = num / den;
}

// ---------------------------------------------------------------------------
// Output broadcast: out[g,n,c] = Wl[c]*S[g,n] + (bl+bias+pos)[t,c]
// block = 20 nodes x 24 c4, single (g, t) per block; wl/ad in smem
// ---------------------------------------------------------------------------
__global__ __launch_bounds__(OTPB) void k_out(const float* __restrict__ Wl,
                                              float4* __restrict__ out) {
    __shared__ float4 s_wl[C4_], s_ad[C4_];
    int bid = blockIdx.x;
    int tid = threadIdx.x;
    int t   = (bid / (N_ / ONODES)) % T_;    // graph's time index (uniform per block)

    if (tid < C4_)               s_wl[tid] = __ldg(&((const float4*)Wl)[tid]);
    else if (tid < 2 * C4_)      s_ad[tid - C4_] = g_add4[t * C4_ + (tid - C4_)];
    __syncthreads();

    int nl  = tid / C4_;                     // node within block (0..19)
    int c4  = tid - nl * C4_;
    int rest = bid * ONODES + nl;            // g*N_ + n

    float  S  = __ldg(&g_S[rest]);
    float4 wl = s_wl[c4];
    float4 ad = s_ad[c4];
    out[rest * C4_ + c4] = make_float4(fmaf(S, wl.x, ad.x), fmaf(S, wl.y, ad.y),
                                       fmaf(S, wl.z, ad.z), fmaf(S, wl.w, ad.w));
}

// ---------------------------------------------------------------------------
extern "C" void kernel_launch(void* const* d_in, const int* in_sizes, int n_in,
                              void* d_out, int out_size) {
    const float* x    = (const float*)d_in[0];
    const int*   EI   = (const int*)  d_in[1];
    const float* Wl   = (const float*)d_in[2];
    const float* bl   = (const float*)d_in[3];
    const float* Wr   = (const float*)d_in[4];
    const float* br   = (const float*)d_in[5];
    const float* att  = (const float*)d_in[6];
    const float* bias = (const float*)d_in[7];

    k_prep   <<<1, 1024>>>(EI, Wl, bl, Wr, br, att, bias);
    k_edge   <<<G_ * 2, TPE>>>(x);
    k_softmax<<<(G_ * N_ + 255) / 256, 256>>>(x);
    k_out    <<<G_ * N_ / ONODES, OTPB>>>(Wl, (float4*)d_out);
}

// round 9
// speedup vs baseline: 1.2960x; 1.2960x over previous
#include <cuda_runtime.h>
#include <math.h>

#define B_    32
#define T_    10
#define N_    1000
#define C_    96
#define E_    8000
#define G_    (B_*T_)      // 320
#define ETOT  (E_+N_)      // 9000 (div by 4)
#define C4_   (C_/4)       // 24
#define CP_   (C_/2)       // 48 channel pairs

// k_out tiling
#define ONODES 20           // nodes per out-block
#define OTPB   (ONODES*C4_) // 480 threads
#define GBLK   (N_/ONODES)  // 50 blocks per graph

// ---- device scratch ----
__device__ ulonglong2 g_Pa[CP_];       // {Wl2, Wr2} packed f32x2 per channel pair
__device__ ulonglong2 g_Pb[CP_];       // {K2,  A2 } K=bl+br, A=0.4*att
__device__ float      g_scal[3];       // 0.6*<att,Wl>, 0.6*<att,Wr>, 0.6*<att,bl+br>
__device__ float4     g_add4[T_*C4_];  // bl+bias+pos per (t, c/4)
__device__ int        g_off[N_+1];
__device__ int4       g_sd4[ETOT/2];   // (src,dst) pairs, 2 edges per int4
__device__ float      g_e[G_*ETOT];    // exp(logit) per (graph, csr slot)

// ---------------------------------------------------------------------------
// Fused prep (R7, proven): params + dots + pos table + CSR
// ---------------------------------------------------------------------------
__device__ __forceinline__ int edge_dst(const int* EI, int e) {
    return (e < E_) ? EI[E_ + e] : (e - E_);
}
__device__ __forceinline__ int edge_src(const int* EI, int e) {
    return (e < E_) ? EI[e] : (e - E_);
}

__global__ void k_prep(const int* __restrict__ EI,
                       const float* __restrict__ Wl, const float* __restrict__ bl,
                       const float* __restrict__ Wr, const float* __restrict__ br,
                       const float* __restrict__ att, const float* __restrict__ bias) {
    __shared__ int   sdeg[1024];
    __shared__ int   soff[N_+1];
    __shared__ int   scnt[N_];
    __shared__ int   stmp[ETOT];
    __shared__ float sred[32];

    int tid  = threadIdx.x;
    int lane = tid & 31;
    int wid  = tid >> 5;

    float d0 = 0.f, d1 = 0.f, d2 = 0.f;
    if (tid < C_) {
        float a = att[tid];
        d0 = a * Wl[tid]; d1 = a * Wr[tid]; d2 = a * (bl[tid] + br[tid]);

        int   pair = tid >> 1;
        float freq = __expf(-(float)(2 * pair) * (logf(10000.f) / (float)C_));
        float badd = bl[tid] + bias[tid];
        float* addf = (float*)g_add4;
        for (int t = 0; t < T_; t++) {
            float arg = (float)t * freq;
            addf[t * C_ + tid] = badd + ((tid & 1) ? cosf(arg) : sinf(arg));
        }
    }
    if (tid < CP_) {
        int c0 = 2 * tid, c1 = 2 * tid + 1;
        float4 pa = make_float4(Wl[c0], Wl[c1], Wr[c0], Wr[c1]);
        float4 pb = make_float4(bl[c0] + br[c0], bl[c1] + br[c1],
                                0.4f * att[c0], 0.4f * att[c1]);
        ((float4*)g_Pa)[tid] = pa;
        ((float4*)g_Pb)[tid] = pb;
    }
    float vals[3] = {d0, d1, d2};
    for (int r = 0; r < 3; r++) {
        float v = vals[r];
        #pragma unroll
        for (int o = 16; o; o >>= 1) v += __shfl_down_sync(0xffffffffu, v, o);
        if (lane == 0) sred[wid] = v;
        __syncthreads();
        if (wid == 0) {
            float w = sred[lane];
            #pragma unroll
            for (int o = 16; o; o >>= 1) w += __shfl_down_sync(0xffffffffu, w, o);
            if (lane == 0) g_scal[r] = 0.6f * w;
        }
        __syncthreads();
    }

    sdeg[tid] = 0;
    if (tid < N_) scnt[tid] = 0;
    __syncthreads();
    for (int e = tid; e < ETOT; e += 1024)
        atomicAdd(&sdeg[edge_dst(EI, e)], 1);
    __syncthreads();

    for (int o = 1; o < 1024; o <<= 1) {
        int t = (tid >= o) ? sdeg[tid - o] : 0;
        __syncthreads();
        sdeg[tid] += t;
        __syncthreads();
    }
    if (tid == 0) soff[0] = 0;
    if (tid < N_) soff[tid + 1] = sdeg[tid];
    __syncthreads();
    if (tid <= N_) g_off[tid] = soff[tid];

    for (int e = tid; e < ETOT; e += 1024) {
        int d = edge_dst(EI, e);
        stmp[soff[d] + atomicAdd(&scnt[d], 1)] = e;
    }
    __syncthreads();

    if (tid < N_) {
        int lo = soff[tid], hi = soff[tid + 1];
        for (int a = lo + 1; a < hi; a++) {
            int key = stmp[a];
            int b = a - 1;
            while (b >= lo && stmp[b] > key) { stmp[b + 1] = stmp[b]; b--; }
            stmp[b + 1] = key;
        }
        int2* sd = (int2*)g_sd4;
        for (int a = lo; a < hi; a++)
            sd[a] = make_int2(edge_src(EI, stmp[a]), tid);
    }
}

// ---------------------------------------------------------------------------
// Packed f32x2 helpers
// ---------------------------------------------------------------------------
typedef unsigned long long ull;
__device__ __forceinline__ ull fma2(ull a, ull b, ull c) {
    ull d;
    asm("fma.rn.f32x2 %0, %1, %2, %3;" : "=l"(d) : "l"(a), "l"(b), "l"(c));
    return d;
}
__device__ __forceinline__ ull pack2(float v) {
    ull u;
    asm("mov.b64 %0, {%1, %1};" : "=l"(u) : "f"(v));
    return u;
}
__device__ __forceinline__ float sum2(ull u) {
    float lo, hi;
    asm("mov.b64 {%0, %1}, %2;" : "=f"(lo), "=f"(hi) : "l"(u));
    return lo + hi;
}
#define ABS2 0x7FFFFFFF7FFFFFFFULL

// ---------------------------------------------------------------------------
// Logits (R7 proven shape): 4 edges/thread, 3 fma2 per channel-pair,
// epilogue stores exp(logit)
// ---------------------------------------------------------------------------
__global__ void k_logits(const float* __restrict__ x) {
    __shared__ ulonglong2 sPa[CP_], sPb[CP_];
    __shared__ float      Ssc[3];
    int tl = threadIdx.x;
    if (tl < CP_) { sPa[tl] = g_Pa[tl]; sPb[tl] = g_Pb[tl]; }
    if (tl < 3)   Ssc[tl] = g_scal[tl];
    __syncthreads();

    int t = blockIdx.x * blockDim.x + tl;
    if (t >= G_ * ETOT / 4) return;
    int base = t * 4;                        // global (graph, edge) index
    int g = base / ETOT;                     // ETOT % 4 == 0 -> same g for all 4
    int s = base - g * ETOT;                 // per-graph CSR slot (s % 4 == 0)
    const float* xg = x + g * N_;

    int4 q0 = __ldg(&g_sd4[(s >> 1)]);       // edges s, s+1
    int4 q1 = __ldg(&g_sd4[(s >> 1) + 1]);   // edges s+2, s+3

    float xj[4], xi[4];
    xj[0] = __ldg(&xg[q0.x]); xi[0] = __ldg(&xg[q0.y]);
    xj[1] = __ldg(&xg[q0.z]); xi[1] = __ldg(&xg[q0.w]);
    xj[2] = __ldg(&xg[q1.x]); xi[2] = __ldg(&xg[q1.y]);
    xj[3] = __ldg(&xg[q1.z]); xi[3] = __ldg(&xg[q1.w]);

    ull xj2[4], xi2[4], acc[4];
    #pragma unroll
    for (int e = 0; e < 4; e++) {
        xj2[e] = pack2(xj[e]); xi2[e] = pack2(xi[e]); acc[e] = 0ULL;
    }

    #pragma unroll 8
    for (int c2 = 0; c2 < CP_; c2++) {
        ulonglong2 pa = sPa[c2];    // {Wl2, Wr2}
        ulonglong2 pb = sPb[c2];    // {K2,  A2 }
        #pragma unroll
        for (int e = 0; e < 4; e++) {
            ull z = fma2(xj2[e], pa.x, fma2(xi2[e], pa.y, pb.x));
            z &= ABS2;
            acc[e] = fma2(pb.y, z, acc[e]);
        }
    }

    #pragma unroll
    for (int e = 0; e < 4; e++) {
        float lin = fmaf(Ssc[0], xj[e], fmaf(Ssc[1], xi[e], Ssc[2]));
        g_e[base + e] = __expf(lin + sum2(acc[e]));   // store exp(logit)
    }
}

// ---------------------------------------------------------------------------
// Fused softmax + output. Block = 20 nodes x 24 c4 of one graph.
// 16 lanes per node sum exp-weights in parallel (shfl reduce, fixed order),
// then the block broadcast-stores out[g,n,c] = Wl[c]*S + (bl+bias+pos)[t,c].
// k_out is DRAM-write-bound, so the softmax latency rides free.
// ---------------------------------------------------------------------------
__global__ __launch_bounds__(OTPB) void k_outfuse(const float* __restrict__ x,
                                                  const float* __restrict__ Wl,
                                                  float4* __restrict__ out) {
    __shared__ float4 s_wl[C4_], s_ad[C4_];
    __shared__ float  s_S[ONODES];
    int bid = blockIdx.x;
    int tid = threadIdx.x;
    int g   = bid / GBLK;                    // graph (uniform per block)
    int t   = g % T_;
    int n0  = (bid - g * GBLK) * ONODES;     // first node of this block

    if (tid >= 320 && tid < 320 + C4_)            s_wl[tid - 320] = __ldg(&((const float4*)Wl)[tid - 320]);
    else if (tid >= 320 + C4_ && tid < 320 + 2*C4_) s_ad[tid - 320 - C4_] = g_add4[t * C4_ + (tid - 320 - C4_)];

    if (tid < 16 * ONODES) {                 // warps 0-9: softmax, 16 lanes/node
        int st = tid >> 4;                   // node within block
        int ln = tid & 15;
        int i  = n0 + st;
        int lo = g_off[i], hi = g_off[i + 1];
        const float* eb = g_e + g * ETOT;
        const float* xg = x + g * N_;
        const int2*  sd = (const int2*)g_sd4;

        float num = 0.f, den = 0.f;
        for (int s = lo + ln; s < hi; s += 16) {
            float w  = eb[s];                // already exp(logit)
            float xv = __ldg(&xg[sd[s].x]);
            num = fmaf(w, xv, num);
            den += w;
        }
        #pragma unroll
        for (int o = 8; o; o >>= 1) {
            num += __shfl_down_sync(0xffffffffu, num, o, 16);
            den += __shfl_down_sync(0xffffffffu, den, o, 16);
        }
        if (ln == 0) s_S[st] = num / den;
    }
    __syncthreads();

    int nl = tid / C4_;
    int c4 = tid - nl * C4_;
    float  S  = s_S[nl];
    float4 wl = s_wl[c4];
    float4 ad = s_ad[c4];
    float4 v  = make_float4(fmaf(S, wl.x, ad.x), fmaf(S, wl.y, ad.y),
                            fmaf(S, wl.z, ad.z), fmaf(S, wl.w, ad.w));
    __stcs(&out[(bid * ONODES + nl) * C4_ + c4], v);
}

// ---------------------------------------------------------------------------
extern "C" void kernel_launch(void* const* d_in, const int* in_sizes, int n_in,
                              void* d_out, int out_size) {
    const float* x    = (const float*)d_in[0];
    const int*   EI   = (const int*)  d_in[1];
    const float* Wl   = (const float*)d_in[2];
    const float* bl   = (const float*)d_in[3];
    const float* Wr   = (const float*)d_in[4];
    const float* br   = (const float*)d_in[5];
    const float* att  = (const float*)d_in[6];
    const float* bias = (const float*)d_in[7];

    k_prep   <<<1, 1024>>>(EI, Wl, bl, Wr, br, att, bias);
    k_logits <<<(G_ * ETOT / 4 + 255) / 256, 256>>>(x);
    k_outfuse<<<G_ * GBLK, OTPB>>>(x, Wl, (float4*)d_out);
}

// round 10
// speedup vs baseline: 1.3314x; 1.0273x over previous
#include <cuda_runtime.h>
#include <math.h>

#define B_    32
#define T_    10
#define N_    1000
#define C_    96
#define E_    8000
#define G_    (B_*T_)      // 320
#define ETOT  (E_+N_)      // 9000 (div by 8)
#define C4_   (C_/4)       // 24
#define CP_   (C_/2)       // 48 channel pairs
#define EPT   8            // edges per thread in k_logits

// ---- device scratch ----
__device__ ulonglong2 g_Pa[CP_];       // {Wl2, Wr2} packed f32x2 per channel pair
__device__ ulonglong2 g_Pb[CP_];       // {K2,  A2 } K=bl+br, A=0.4*att
__device__ float      g_scal[3];       // 0.6*<att,Wl>, 0.6*<att,Wr>, 0.6*<att,bl+br>
__device__ float4     g_add4[T_*C4_];  // bl+bias+pos per (t, c/4)
__device__ int        g_deg[N_];
__device__ int        g_off[N_+1];
__device__ int4       g_sd4[ETOT/2];   // (src,dst) pairs, 2 edges per int4
__device__ float      g_e[G_*ETOT];    // logits
__device__ float      g_S[G_*N_];      // softmax-weighted source mean

__device__ __forceinline__ int edge_dst(const int* EI, int e) {
    return (e < E_) ? EI[E_ + e] : (e - E_);
}
__device__ __forceinline__ int edge_src(const int* EI, int e) {
    return (e < E_) ? EI[e] : (e - E_);
}

// ---------------------------------------------------------------------------
// Params: packed tables + 3 scalar dots + pos table + zero g_deg (1 block,128)
// ---------------------------------------------------------------------------
__global__ void k_params(const float* __restrict__ Wl, const float* __restrict__ bl,
                         const float* __restrict__ Wr, const float* __restrict__ br,
                         const float* __restrict__ att, const float* __restrict__ bias) {
    __shared__ float sred[3][4];
    int tid  = threadIdx.x;          // 128
    int lane = tid & 31;
    int wid  = tid >> 5;

    for (int i = tid; i < N_; i += 128) g_deg[i] = 0;

    float d0 = 0.f, d1 = 0.f, d2 = 0.f;
    if (tid < C_) {
        float a = att[tid];
        d0 = a * Wl[tid]; d1 = a * Wr[tid]; d2 = a * (bl[tid] + br[tid]);

        int   pair = tid >> 1;
        float freq = __expf(-(float)(2 * pair) * (logf(10000.f) / (float)C_));
        float badd = bl[tid] + bias[tid];
        float* addf = (float*)g_add4;
        for (int t = 0; t < T_; t++) {
            float arg = (float)t * freq;
            addf[t * C_ + tid] = badd + ((tid & 1) ? cosf(arg) : sinf(arg));
        }
    }
    if (tid < CP_) {
        int c0 = 2 * tid, c1 = 2 * tid + 1;
        float4 pa = make_float4(Wl[c0], Wl[c1], Wr[c0], Wr[c1]);
        float4 pb = make_float4(bl[c0] + br[c0], bl[c1] + br[c1],
                                0.4f * att[c0], 0.4f * att[c1]);
        ((float4*)g_Pa)[tid] = pa;
        ((float4*)g_Pb)[tid] = pb;
    }
    float vals[3] = {d0, d1, d2};
    #pragma unroll
    for (int r = 0; r < 3; r++) {
        float v = vals[r];
        #pragma unroll
        for (int o = 16; o; o >>= 1) v += __shfl_down_sync(0xffffffffu, v, o);
        if (lane == 0) sred[r][wid] = v;
    }
    __syncthreads();
    if (tid < 3)
        g_scal[tid] = 0.6f * (sred[tid][0] + sred[tid][1] + sred[tid][2] + sred[tid][3]);
}

// ---------------------------------------------------------------------------
// Histogram of in-degrees (global atomics, spread addresses)
// ---------------------------------------------------------------------------
__global__ void k_hist(const int* __restrict__ EI) {
    int e = blockIdx.x * blockDim.x + threadIdx.x;
    if (e >= ETOT) return;
    atomicAdd(&g_deg[edge_dst(EI, e)], 1);
}

// ---------------------------------------------------------------------------
// Exclusive scan over 1000 degrees (1 block)
// ---------------------------------------------------------------------------
__global__ void k_scan() {
    __shared__ int s[1024];
    int tid = threadIdx.x;
    s[tid] = (tid < N_) ? g_deg[tid] : 0;
    __syncthreads();
    for (int o = 1; o < 1024; o <<= 1) {
        int t = (tid >= o) ? s[tid - o] : 0;
        __syncthreads();
        s[tid] += t;
        __syncthreads();
    }
    if (tid == 0) g_off[0] = 0;
    if (tid < N_) g_off[tid + 1] = s[tid];
}

// ---------------------------------------------------------------------------
// Warp-per-edge deterministic rank scatter: rank = #{e' < e : dst同}, emitted
// directly in edge-id order (== sorted CSR). EI (36 KB) is L1-resident.
// ---------------------------------------------------------------------------
__global__ void k_scatter(const int* __restrict__ EI) {
    int gw   = (blockIdx.x * blockDim.x + threadIdx.x) >> 5;
    int lane = threadIdx.x & 31;
    if (gw >= ETOT) return;
    int d = edge_dst(EI, gw);
    int cnt = 0;
    for (int e = lane; e < gw; e += 32)
        cnt += (edge_dst(EI, e) == d);
    #pragma unroll
    for (int o = 16; o; o >>= 1) cnt += __shfl_down_sync(0xffffffffu, cnt, o);
    if (lane == 0) {
        int slot = g_off[d] + cnt;
        ((int2*)g_sd4)[slot] = make_int2(edge_src(EI, gw), d);
    }
}

// ---------------------------------------------------------------------------
// Packed f32x2 helpers
// ---------------------------------------------------------------------------
typedef unsigned long long ull;
__device__ __forceinline__ ull fma2(ull a, ull b, ull c) {
    ull d;
    asm("fma.rn.f32x2 %0, %1, %2, %3;" : "=l"(d) : "l"(a), "l"(b), "l"(c));
    return d;
}
__device__ __forceinline__ ull pack2(float v) {
    ull u;
    asm("mov.b64 %0, {%1, %1};" : "=l"(u) : "f"(v));
    return u;
}
__device__ __forceinline__ float sum2(ull u) {
    float lo, hi;
    asm("mov.b64 {%0, %1}, %2;" : "=f"(lo), "=f"(hi) : "l"(u));
    return lo + hi;
}
__device__ __forceinline__ float lo2(ull u) {
    float lo, hi;
    asm("mov.b64 {%0, %1}, %2;" : "=f"(lo), "=f"(hi) : "l"(u));
    return lo;
}
#define ABS2 0x7FFFFFFF7FFFFFFFULL

// ---------------------------------------------------------------------------
// Logits: 8 edges/thread (halves LDS per edge vs R7), 3 fma2/channel-pair
// e = S0*xj + S1*xi + S2 + sum_c 0.4*att[c]*|xj*Wl[c] + xi*Wr[c] + K[c]|
// ---------------------------------------------------------------------------
__global__ __launch_bounds__(128) void k_logits(const float* __restrict__ x) {
    __shared__ ulonglong2 sPa[CP_], sPb[CP_];
    __shared__ float      Ssc[3];
    int tl = threadIdx.x;
    if (tl < CP_) { sPa[tl] = g_Pa[tl]; sPb[tl] = g_Pb[tl]; }
    if (tl < 3)   Ssc[tl] = g_scal[tl];
    __syncthreads();

    int t = blockIdx.x * blockDim.x + tl;
    if (t >= G_ * ETOT / EPT) return;
    int base = t * EPT;                      // global (graph, edge) index
    int g = base / ETOT;                     // ETOT % 8 == 0 -> same g for all 8
    int s = base - g * ETOT;                 // per-graph CSR slot
    const float* xg = x + g * N_;

    ull xj2[EPT], xi2[EPT], acc[EPT];
    #pragma unroll
    for (int q = 0; q < EPT / 2; q++) {
        int4 sd = __ldg(&g_sd4[(s >> 1) + q]);
        xj2[2*q]   = pack2(__ldg(&xg[sd.x]));
        xi2[2*q]   = pack2(__ldg(&xg[sd.y]));
        xj2[2*q+1] = pack2(__ldg(&xg[sd.z]));
        xi2[2*q+1] = pack2(__ldg(&xg[sd.w]));
        acc[2*q] = 0ULL; acc[2*q+1] = 0ULL;
    }

    #pragma unroll 4
    for (int c2 = 0; c2 < CP_; c2++) {
        ulonglong2 pa = sPa[c2];    // {Wl2, Wr2}
        ulonglong2 pb = sPb[c2];    // {K2,  A2 }
        #pragma unroll
        for (int e = 0; e < EPT; e++) {
            ull z = fma2(xj2[e], pa.x, fma2(xi2[e], pa.y, pb.x));
            z &= ABS2;
            acc[e] = fma2(pb.y, z, acc[e]);
        }
    }

    #pragma unroll
    for (int e = 0; e < EPT; e++) {
        float lin = fmaf(Ssc[0], lo2(xj2[e]), fmaf(Ssc[1], lo2(xi2[e]), Ssc[2]));
        g_e[base + e] = lin + sum2(acc[e]);
    }
}

// ---------------------------------------------------------------------------
// Per-node softmax (R7-proven; no max pass, logits bounded)
// ---------------------------------------------------------------------------
__global__ void k_softmax(const float* __restrict__ x) {
    int tid = blockIdx.x * blockDim.x + threadIdx.x;
    if (tid >= G_ * N_) return;
    int g = tid / N_;
    int i = tid - g * N_;
    int lo = g_off[i], hi = g_off[i + 1];
    const float* eb = g_e + g * ETOT;
    const float* xg = x + g * N_;
    const int2*  sd = (const int2*)g_sd4;

    float num = 0.f, den = 0.f;
    for (int s = lo; s < hi; s++) {
        float w  = __expf(eb[s]);
        float xj = __ldg(&xg[sd[s].x]);
        num = fmaf(w, xj, num);
        den += w;
    }
    g_S[tid] = num / den;
}

// ---------------------------------------------------------------------------
// Output broadcast (R7-proven, HBM-write-drain bound)
// ---------------------------------------------------------------------------
__global__ void k_out(const float* __restrict__ Wl, float4* __restrict__ out) {
    int tid = blockIdx.x * blockDim.x + threadIdx.x;
    if (tid >= G_ * N_ * C4_) return;
    int c4   = tid % C4_;
    int rest = tid / C4_;          // g*N_ + n
    int g    = rest / N_;
    int t    = g % T_;

    float  S  = __ldg(&g_S[rest]);
    float4 wl = __ldg(&((const float4*)Wl)[c4]);
    float4 ad = __ldg(&g_add4[t * C4_ + c4]);
    out[tid] = make_float4(fmaf(S, wl.x, ad.x), fmaf(S, wl.y, ad.y),
                           fmaf(S, wl.z, ad.z), fmaf(S, wl.w, ad.w));
}

// ---------------------------------------------------------------------------
extern "C" void kernel_launch(void* const* d_in, const int* in_sizes, int n_in,
                              void* d_out, int out_size) {
    const float* x    = (const float*)d_in[0];
    const int*   EI   = (const int*)  d_in[1];
    const float* Wl   = (const float*)d_in[2];
    const float* bl   = (const float*)d_in[3];
    const float* Wr   = (const float*)d_in[4];
    const float* br   = (const float*)d_in[5];
    const float* att  = (const float*)d_in[6];
    const float* bias = (const float*)d_in[7];

    k_params <<<1, 128>>>(Wl, bl, Wr, br, att, bias);
    k_hist   <<<(ETOT + 255) / 256, 256>>>(EI);
    k_scan   <<<1, 1024>>>();
    k_scatter<<<(ETOT * 32 + 255) / 256, 256>>>(EI);
    k_logits <<<(G_ * ETOT / EPT + 127) / 128, 128>>>(x);
    k_softmax<<<(G_ * N_ + 255) / 256, 256>>>(x);
    k_out    <<<(G_ * N_ * C4_ + 255) / 256, 256>>>(Wl, (float4*)d_out);
}